// round 5
// baseline (speedup 1.0000x reference)
#include <cuda_runtime.h>
#include <cstdint>

// FPS + gather, bit-exact vs JAX/XLA reference (distance = fma(dz,dz,fma(dx,dx,rn(dy*dy)))).
// B=8, N=131072, S=4096.
//
// R4: sync rearchitecture, compute loop arithmetic UNCHANGED from R3 (rel_err 0.0).
//  - 16 CTAs/batch = 2 clusters of 8. Intra-cluster barrier: DSMEM mbarrier
//    (arrive ~215cyc, try_wait wakeup ~60cyc) with partials (v,idx,x,y,z)
//    pushed into every peer's smem -> winner read from local smem (29cyc).
//  - Cross-cluster (2 parties): single tagged release/acquire L2 record.
//  - Coords carried through reductions; no post-barrier gather.
//  - prep merged into one kernel so ncu -s5 captures the main kernel.

#define NB 8
#define NP 131072
#define NS 4096
#define CPB 16                 // CTAs per batch
#define NT 512                 // threads per CTA
#define ROUNDS (NS - 1)
#define PPC (NP / CPB)         // 8192 points per CTA
#define CHUNK 4                // 4 float4 per coord per thread = 16 pts/thread
#define CLU 8                  // CTAs per cluster

__device__ float g_x[NB * NP];
__device__ float g_y[NB * NP];
__device__ float g_z[NB * NP];

struct __align__(32) Xch { unsigned long long key; unsigned long long pad; float4 xyz; };
__device__ Xch g_xch[2][NB][2];   // [parity][batch][cluster]

__global__ void fps_prep_kernel(const float* __restrict__ pts) {
    // poison cross-cluster slots (tag 0 never matches expected tags >= 1)
    if (blockIdx.x == 0 && threadIdx.x < 2 * NB * 2) {
        ((Xch*)g_xch)[threadIdx.x].key = 0ull;
    }
    int i = blockIdx.x * blockDim.x + threadIdx.x;
    int stride = gridDim.x * blockDim.x;
    for (; i < NB * NP; i += stride) {
        g_x[i] = pts[3 * i + 0];
        g_y[i] = pts[3 * i + 1];
        g_z[i] = pts[3 * i + 2];
    }
}

__device__ __forceinline__ uint32_t smem_u32(const void* p) {
    uint32_t a;
    asm("{ .reg .u64 t; cvta.to.shared.u64 t, %1; cvt.u32.u64 %0, t; }" : "=r"(a) : "l"(p));
    return a;
}
__device__ __forceinline__ uint32_t ctarank() {
    uint32_t r; asm("mov.u32 %0, %%cluster_ctarank;" : "=r"(r)); return r;
}

#define MBAR_INIT(addr, cnt) \
    asm volatile("mbarrier.init.shared.b64 [%0], %1;" :: "r"(addr), "r"(cnt) : "memory")

// store 5-word record into peer's smem slot (DSMEM)
#define ST_SLOT(laddr, rank, v0, v1, v2, v3, v4) \
    asm volatile("{\n\t.reg .b32 ra;\n\t" \
        "mapa.shared::cluster.u32 ra, %0, %1;\n\t" \
        "st.shared::cluster.b32 [ra],    %2;\n\t" \
        "st.shared::cluster.b32 [ra+4],  %3;\n\t" \
        "st.shared::cluster.b32 [ra+8],  %4;\n\t" \
        "st.shared::cluster.b32 [ra+12], %5;\n\t" \
        "st.shared::cluster.b32 [ra+16], %6;\n\t}" \
        :: "r"(laddr), "r"(rank), "r"(v0), "r"(v1), "r"(v2), "r"(v3), "r"(v4) : "memory")

#define MBAR_ARRIVE_REMOTE(lmbar, rank) \
    asm volatile("{\n\t.reg .b32 ra;\n\t" \
        "mapa.shared::cluster.u32 ra, %0, %1;\n\t" \
        "mbarrier.arrive.shared::cluster.b64 _, [ra];\n\t}" \
        :: "r"(lmbar), "r"(rank) : "memory")

#define MBAR_TRYWAIT_ACQ_CLUSTER(mbar, parity) do { \
    uint32_t _m = (mbar), _p = (parity), _done; \
    asm volatile("{\n\t.reg .pred p;\n\t" \
        "mbarrier.try_wait.parity.acquire.cluster.shared::cta.b64 p, [%1], %2;\n\t" \
        "selp.b32 %0, 1, 0, p;\n\t}" : "=r"(_done) : "r"(_m), "r"(_p) : "memory"); \
    if (!_done) { \
        asm volatile("{\n\t.reg .pred P1;\n\t" \
            "WL_%=:\n\t" \
            "mbarrier.try_wait.parity.acquire.cluster.shared::cta.b64 P1, [%0], %1, 0x989680;\n\t" \
            "@P1 bra.uni WD_%=;\n\t" \
            "bra.uni WL_%=;\n\t" \
            "WD_%=:\n\t}" :: "r"(_m), "r"(_p) : "memory"); \
    } \
} while (0)

__global__ void __launch_bounds__(NT, 1) __cluster_dims__(CLU, 1, 1)
fps_main_kernel(float* __restrict__ out) {
    const int b    = blockIdx.x / CPB;
    const int cl   = (blockIdx.x >> 3) & 1;   // cluster within batch
    const int c    = blockIdx.x % CPB;        // CTA within batch (0..15)
    const unsigned crank = ctarank();         // 0..7 within cluster
    const int tid  = threadIdx.x;
    const int lane = tid & 31;
    const int wid  = tid >> 5;
    const int base = c * PPC;

    const float4* __restrict__ x4 = (const float4*)(g_x + b * NP + base);
    const float4* __restrict__ y4 = (const float4*)(g_y + b * NP + base);
    const float4* __restrict__ z4 = (const float4*)(g_z + b * NP + base);

    float md[CHUNK * 4];
#pragma unroll
    for (int i = 0; i < CHUNK * 4; ++i) md[i] = 1e10f;   // BIG

    __shared__ float s_wv[16]; __shared__ int s_wi[16];
    __shared__ float s_wx[16]; __shared__ float s_wy[16]; __shared__ float s_wz[16];
    __shared__ float s_win[3];
    __shared__ __align__(8)  unsigned long long s_mbar[2];
    __shared__ __align__(16) uint32_t s_slot[2][CLU][8];  // [parity][src][v,i,x,y,z,...]

    const uint32_t mbar_a[2] = { smem_u32(&s_mbar[0]), smem_u32(&s_mbar[1]) };

    if (tid == 0) { MBAR_INIT(mbar_a[0], CLU); MBAR_INIT(mbar_a[1], CLU); }
    __syncthreads();
    asm volatile("barrier.cluster.arrive.aligned;" ::: "memory");
    asm volatile("barrier.cluster.wait.aligned;"   ::: "memory");

    float lx = g_x[b * NP + 0];
    float ly = g_y[b * NP + 0];
    float lz = g_z[b * NP + 0];

    if (c == 0 && tid == 0) {
        out[(b * NS + 0) * 3 + 0] = lx;
        out[(b * NS + 0) * 3 + 1] = ly;
        out[(b * NS + 0) * 3 + 2] = lz;
    }

    for (int r = 0; r < ROUNDS; ++r) {
        float bestv = -1.0f;
        int   besti = 0x7fffffff;

#pragma unroll
        for (int j = 0; j < CHUNK; ++j) {
            const int e = j * NT + tid;
            float4 X = x4[e];
            float4 Y = y4[e];
            float4 Z = z4[e];
            float xv[4] = {X.x, X.y, X.z, X.w};
            float yv[4] = {Y.x, Y.y, Y.z, Y.w};
            float zv[4] = {Z.x, Z.y, Z.z, Z.w};
            const int idx0 = base + e * 4;
#pragma unroll
            for (int k = 0; k < 4; ++k) {
                // FROZEN arithmetic: fma(dz,dz, fma(dx,dx, rn(dy*dy)))
                float dx = __fsub_rn(xv[k], lx);
                float dy = __fsub_rn(yv[k], ly);
                float dz = __fsub_rn(zv[k], lz);
                float d  = __fmaf_rn(dz, dz,
                           __fmaf_rn(dx, dx,
                           __fmul_rn(dy, dy)));
                float m  = fminf(md[j * 4 + k], d);
                md[j * 4 + k] = m;
                if (m > bestv) { bestv = m; besti = idx0 + k; }
            }
        }

        // warp argmax (tiebreak: smaller index)
#pragma unroll
        for (int off = 16; off > 0; off >>= 1) {
            float ov = __shfl_down_sync(0xffffffffu, bestv, off);
            int   oi = __shfl_down_sync(0xffffffffu, besti, off);
            if (ov > bestv || (ov == bestv && oi < besti)) { bestv = ov; besti = oi; }
        }
        if (lane == 0) {
            // warp leader attaches coords of its winner (L1-resident, pre-barrier)
            s_wv[wid] = bestv; s_wi[wid] = besti;
            s_wx[wid] = g_x[b * NP + besti];
            s_wy[wid] = g_y[b * NP + besti];
            s_wz[wid] = g_z[b * NP + besti];
        }
        __syncthreads();

        if (wid == 0) {
            const int par = r & 1;
            // CTA reduce over 16 warp records, bfly so lanes 0..15 all hold result
            float v = (lane < 16) ? s_wv[lane] : -2.0f;
            int   i = (lane < 16) ? s_wi[lane] : 0x7fffffff;
            float x = (lane < 16) ? s_wx[lane] : 0.0f;
            float y = (lane < 16) ? s_wy[lane] : 0.0f;
            float z = (lane < 16) ? s_wz[lane] : 0.0f;
#pragma unroll
            for (int off = 8; off > 0; off >>= 1) {
                float ov = __shfl_xor_sync(0xffffffffu, v, off);
                int   oi = __shfl_xor_sync(0xffffffffu, i, off);
                float ox = __shfl_xor_sync(0xffffffffu, x, off);
                float oy = __shfl_xor_sync(0xffffffffu, y, off);
                float oz = __shfl_xor_sync(0xffffffffu, z, off);
                if (ov > v || (ov == v && oi < i)) { v = ov; i = oi; x = ox; y = oy; z = oz; }
            }

            // push this CTA's record into every cluster peer's smem, then arrive
            if (lane < CLU) {
                uint32_t laddr = smem_u32(&s_slot[par][crank][0]);
                ST_SLOT(laddr, lane, __float_as_uint(v), (uint32_t)i,
                        __float_as_uint(x), __float_as_uint(y), __float_as_uint(z));
            }
            asm volatile("fence.acq_rel.cluster;" ::: "memory");
            if (lane < CLU) MBAR_ARRIVE_REMOTE(mbar_a[par], lane);

            // wait for all 8 cluster CTAs
            MBAR_TRYWAIT_ACQ_CLUSTER(mbar_a[par], (r >> 1) & 1);

            // cluster reduce over 8 records (local smem)
            float cv; int ci; float cx, cy, cz;
            if (lane < CLU) {
                const uint32_t* sp = &s_slot[par][lane][0];
                cv = __uint_as_float(sp[0]); ci = (int)sp[1];
                cx = __uint_as_float(sp[2]); cy = __uint_as_float(sp[3]);
                cz = __uint_as_float(sp[4]);
            } else { cv = -2.0f; ci = 0x7fffffff; cx = cy = cz = 0.0f; }
#pragma unroll
            for (int off = 4; off > 0; off >>= 1) {
                float ov = __shfl_xor_sync(0xffffffffu, cv, off);
                int   oi = __shfl_xor_sync(0xffffffffu, ci, off);
                float ox = __shfl_xor_sync(0xffffffffu, cx, off);
                float oy = __shfl_xor_sync(0xffffffffu, cy, off);
                float oz = __shfl_xor_sync(0xffffffffu, cz, off);
                if (ov > cv || (ov == cv && oi < ci)) { cv = ov; ci = oi; cx = ox; cy = oy; cz = oz; }
            }

            if (lane == 0) {
                // cross-cluster exchange via tagged release/acquire L2 record
                Xch* mine = &g_xch[par][b][cl];
                Xch* oth  = &g_xch[par][b][cl ^ 1];
                unsigned long long key =
                    ((unsigned long long)__float_as_uint(cv) << 32) |
                    ((unsigned long long)(unsigned)(r + 1) << 18) |
                    (unsigned)ci;
                asm volatile("st.global.v4.f32 [%0], {%1,%2,%3,%4};"
                             :: "l"(&mine->xyz), "f"(cx), "f"(cy), "f"(cz), "f"(0.0f) : "memory");
                asm volatile("st.release.gpu.global.b64 [%0], %1;"
                             :: "l"(&mine->key), "l"(key) : "memory");
                unsigned long long k;
                do {
                    asm volatile("ld.acquire.gpu.global.b64 %0, [%1];"
                                 : "=l"(k) : "l"(&oth->key) : "memory");
                } while ((((unsigned)(k >> 18)) & 0xFFFu) != (unsigned)(r + 1));
                float ox, oy, oz, ow;
                asm volatile("ld.global.cg.v4.f32 {%0,%1,%2,%3}, [%4];"
                             : "=f"(ox), "=f"(oy), "=f"(oz), "=f"(ow) : "l"(&oth->xyz) : "memory");
                float ovv = __uint_as_float((unsigned)(k >> 32));
                int   oii = (int)((unsigned)k & 0x1FFFFu);
                if (ovv > cv || (ovv == cv && oii < ci)) { cv = ovv; ci = oii; cx = ox; cy = oy; cz = oz; }

                s_win[0] = cx; s_win[1] = cy; s_win[2] = cz;
                if (c == 0) {
                    out[(b * NS + r + 1) * 3 + 0] = cx;
                    out[(b * NS + r + 1) * 3 + 1] = cy;
                    out[(b * NS + r + 1) * 3 + 2] = cz;
                }
            }
        }
        __syncthreads();
        lx = s_win[0]; ly = s_win[1]; lz = s_win[2];
    }
}

extern "C" void kernel_launch(void* const* d_in, const int* in_sizes, int n_in,
                              void* d_out, int out_size) {
    const float* pts = (const float*)d_in[0];
    float* out = (float*)d_out;
    (void)in_sizes; (void)n_in; (void)out_size;

    fps_prep_kernel<<<512, 256>>>(pts);
    fps_main_kernel<<<NB * CPB, NT>>>(out);
}

// round 6
// speedup vs baseline: 2.0568x; 2.0568x over previous
#include <cuda_runtime.h>
#include <cstdint>

// FPS + gather, bit-exact vs JAX/XLA (distance = fma(dz,dz, fma(dx,dx, rn(dy*dy)))).
// B=8, N=131072, S=4096.
//
// R5: no clusters (R4's cluster-scope fences flushed L1D every round -> 2.5x
// regression). R3 skeleton + atomic-free fence-free sync:
//   each CTA release-stores one tagged u64 partial (value|tag|idx) into a
//   per-batch 128B slot line; all CTAs poll all 16 slots in parallel
//   (one lane per slot, ld.acquire.gpu), then redundantly bfly-reduce.
// No atomics, no membar, no second publication trip. Compute loop frozen.

#define NB 8
#define NP 131072
#define NS 4096
#define CPB 16                 // CTAs per batch
#define NT 512                 // threads per CTA
#define ROUNDS (NS - 1)
#define PPC (NP / CPB)         // 8192 points per CTA
#define CHUNK 4                // 4 float4 per coord per thread = 16 pts/thread

__device__ float g_x[NB * NP];
__device__ float g_y[NB * NP];
__device__ float g_z[NB * NP];
// [parity][batch][cta] tagged partials; one 128B line per (parity,batch)
__device__ __align__(128) unsigned long long g_slot[2][NB][CPB];

__global__ void fps_prep_kernel(const float* __restrict__ pts) {
    if (blockIdx.x == 0 && threadIdx.x < 2 * NB * CPB) {
        ((unsigned long long*)g_slot)[threadIdx.x] = 0ull;   // tag 0 != any r+1
    }
    int i = blockIdx.x * blockDim.x + threadIdx.x;
    int stride = gridDim.x * blockDim.x;
    for (; i < NB * NP; i += stride) {
        g_x[i] = pts[3 * i + 0];
        g_y[i] = pts[3 * i + 1];
        g_z[i] = pts[3 * i + 2];
    }
}

__global__ void __launch_bounds__(NT, 1) fps_main_kernel(float* __restrict__ out) {
    const int b    = blockIdx.x / CPB;
    const int c    = blockIdx.x % CPB;
    const int tid  = threadIdx.x;
    const int lane = tid & 31;
    const int wid  = tid >> 5;
    const int base = c * PPC;

    const float4* __restrict__ x4 = (const float4*)(g_x + b * NP + base);
    const float4* __restrict__ y4 = (const float4*)(g_y + b * NP + base);
    const float4* __restrict__ z4 = (const float4*)(g_z + b * NP + base);

    float md[CHUNK * 4];
#pragma unroll
    for (int i = 0; i < CHUNK * 4; ++i) md[i] = 1e10f;   // BIG

    __shared__ float s_v[NT / 32];
    __shared__ int   s_i[NT / 32];
    __shared__ float s_win[3];

    // selection 0 is always index 0
    float lx = g_x[b * NP + 0];
    float ly = g_y[b * NP + 0];
    float lz = g_z[b * NP + 0];

    if (c == 0 && tid == 0) {
        out[(b * NS + 0) * 3 + 0] = lx;
        out[(b * NS + 0) * 3 + 1] = ly;
        out[(b * NS + 0) * 3 + 2] = lz;
    }

    for (int r = 0; r < ROUNDS; ++r) {
        float bestv = -1.0f;
        int   besti = 0x7fffffff;

#pragma unroll
        for (int j = 0; j < CHUNK; ++j) {
            const int e = j * NT + tid;
            float4 X = x4[e];
            float4 Y = y4[e];
            float4 Z = z4[e];
            float xv[4] = {X.x, X.y, X.z, X.w};
            float yv[4] = {Y.x, Y.y, Y.z, Y.w};
            float zv[4] = {Z.x, Z.y, Z.z, Z.w};
            const int idx0 = base + e * 4;
#pragma unroll
            for (int k = 0; k < 4; ++k) {
                // FROZEN arithmetic (rel_err 0.0): fma(dz,dz, fma(dx,dx, rn(dy*dy)))
                float dx = __fsub_rn(xv[k], lx);
                float dy = __fsub_rn(yv[k], ly);
                float dz = __fsub_rn(zv[k], lz);
                float d  = __fmaf_rn(dz, dz,
                           __fmaf_rn(dx, dx,
                           __fmul_rn(dy, dy)));
                float m  = fminf(md[j * 4 + k], d);
                md[j * 4 + k] = m;
                // ascending index + strict '>' == first-occurrence argmax
                if (m > bestv) { bestv = m; besti = idx0 + k; }
            }
        }

        // warp argmax (tiebreak: smaller index)
#pragma unroll
        for (int off = 16; off > 0; off >>= 1) {
            float ov = __shfl_down_sync(0xffffffffu, bestv, off);
            int   oi = __shfl_down_sync(0xffffffffu, besti, off);
            if (ov > bestv || (ov == bestv && oi < besti)) { bestv = ov; besti = oi; }
        }
        if (lane == 0) { s_v[wid] = bestv; s_i[wid] = besti; }
        __syncthreads();

        if (wid == 0) {
            const int par = r & 1;
            const unsigned tag = (unsigned)(r + 1) & 0x1FFFu;

            // CTA reduce over 16 warp records
            float v = (lane < 16) ? s_v[lane] : -2.0f;
            int   i = (lane < 16) ? s_i[lane] : 0x7fffffff;
#pragma unroll
            for (int off = 8; off > 0; off >>= 1) {
                float ov = __shfl_down_sync(0xffffffffu, v, off);
                int   oi = __shfl_down_sync(0xffffffffu, i, off);
                if (ov > v || (ov == v && oi < i)) { v = ov; i = oi; }
            }
            if (lane == 0) {
                // single tagged release store: value(32) | tag(13) | idx(17)
                unsigned long long key =
                    ((unsigned long long)__float_as_uint(v) << 32) |
                    ((unsigned long long)tag << 17) |
                    (unsigned)i;
                asm volatile("st.release.gpu.global.b64 [%0], %1;"
                             :: "l"(&g_slot[par][b][c]), "l"(key) : "memory");
            }

            // all 16 slots polled in parallel, one lane each
            float pv; int pi;
            if (lane < CPB) {
                unsigned long long k;
                const unsigned long long* sp = &g_slot[par][b][lane];
                do {
                    asm volatile("ld.acquire.gpu.global.b64 %0, [%1];"
                                 : "=l"(k) : "l"(sp) : "memory");
                } while ((((unsigned)(k >> 17)) & 0x1FFFu) != tag);
                pv = __uint_as_float((unsigned)(k >> 32));
                pi = (int)((unsigned)k & 0x1FFFFu);
            } else { pv = -2.0f; pi = 0x7fffffff; }

            // redundant bfly reduce: every CTA derives the same winner
#pragma unroll
            for (int off = 8; off > 0; off >>= 1) {
                float ov = __shfl_xor_sync(0xffffffffu, pv, off);
                int   oi = __shfl_xor_sync(0xffffffffu, pi, off);
                if (ov > pv || (ov == pv && oi < pi)) { pv = ov; pi = oi; }
            }

            if (lane == 0) {
                // immutable arrays: plain loads are safe (L1 or L2)
                float wx = g_x[b * NP + pi];
                float wy = g_y[b * NP + pi];
                float wz = g_z[b * NP + pi];
                s_win[0] = wx; s_win[1] = wy; s_win[2] = wz;
                if (c == 0) {
                    out[(b * NS + r + 1) * 3 + 0] = wx;
                    out[(b * NS + r + 1) * 3 + 1] = wy;
                    out[(b * NS + r + 1) * 3 + 2] = wz;
                }
            }
        }
        __syncthreads();
        lx = s_win[0]; ly = s_win[1]; lz = s_win[2];
    }
}

extern "C" void kernel_launch(void* const* d_in, const int* in_sizes, int n_in,
                              void* d_out, int out_size) {
    const float* pts = (const float*)d_in[0];
    float* out = (float*)d_out;
    (void)in_sizes; (void)n_in; (void)out_size;

    fps_prep_kernel<<<512, 256>>>(pts);
    fps_main_kernel<<<NB * CPB, NT>>>(out);
}